// round 10
// baseline (speedup 1.0000x reference)
#include <cuda_runtime.h>
#include <cstdint>

// Problem constants: student/teacher [B=2, V=2, C=64, HW=1024], labels [2,2,1024]
#define N_TOT  4096   // B*V*HW
#define C_DIM  64
#define HW_DIM 1024
#define NIMG   2048   // V*HW  (only same-image pairs contribute)
#define RTILE  16     // anchor rows per block
#define JCHUNK 512    // columns per chunk (within one view)
#define CSLICE 8      // c-rows staged per smem slice

// Scratch (device globals: no allocation allowed)
__device__ float g_tinv10[N_TOT];      // 10 / ||t_j||
__device__ float g_mlpp[N_TOT];
__device__ float g_cnt[N_TOT];
__device__ unsigned int g_ticket = 0;  // last-block ticket (self-resetting)

// ---------- packed f32x2 helpers (Blackwell FFMA2 via PTX) ----------
__device__ __forceinline__ unsigned long long pack2(float lo, float hi) {
    unsigned long long r;
    asm("mov.b64 %0, {%1, %2};" : "=l"(r) : "f"(lo), "f"(hi));
    return r;
}
__device__ __forceinline__ void unpack2(unsigned long long v, float& lo, float& hi) {
    asm("mov.b64 {%0, %1}, %2;" : "=f"(lo), "=f"(hi) : "l"(v));
}
__device__ __forceinline__ unsigned long long ffma2(unsigned long long a,
                                                    unsigned long long b,
                                                    unsigned long long c) {
    unsigned long long d;
    asm("fma.rn.f32x2 %0, %1, %2, %3;" : "=l"(d) : "l"(a), "l"(b), "l"(c));
    return d;
}

// ---------- kernel 1: teacher inverse norms (high-MLP, 32 blocks) ----------
__global__ __launch_bounds__(128) void scl_tnorms_kernel(const float* __restrict__ tea) {
    int n = blockIdx.x * 128 + threadIdx.x;
    const float* base = tea + (size_t)(n >> 10) * C_DIM * HW_DIM + (n & (HW_DIM - 1));
    float ss = 0.f;
#pragma unroll
    for (int c = 0; c < C_DIM; c++) {
        float v = base[c * HW_DIM];
        ss += v * v;
    }
    g_tinv10[n] = 10.f * rsqrtf(fmaxf(ss, 1e-24f));
}

// ---------- kernel 2: fused GEMM + masked log-softmax + final reduce ----------
// Block = 16 anchor rows x 2048 cols (4 chunks of 512). Thread tile 4x8.
// tid: cg = tid & 63 (8-col group), rg = tid >> 6 (4-row group).
__global__ __launch_bounds__(256) void scl_main_kernel(
    const float* __restrict__ stu, const float* __restrict__ tea,
    const int* __restrict__ labels, float* __restrict__ out) {
    __shared__ __align__(16) float ts_s[2][CSLICE][JCHUNK];          // double buffer
    __shared__ __align__(16) unsigned long long sf2_s[C_DIM][RTILE]; // student dup-pairs
    __shared__ float sinv_s[RTILE];
    __shared__ int   lab_s[RTILE];
    __shared__ float redZ[8][4], redS[8][4], redC[8][4];
    __shared__ int islast;

    int tid = threadIdx.x;
    int cg  = tid & 63;
    int rg  = tid >> 6;
    int i0  = blockIdx.x * RTILE;
    int bv_i = i0 >> 10;
    int p_i  = i0 & (HW_DIM - 1);
    int jbase = i0 & ~(NIMG - 1);

    // staging address split (per-thread, reused for all slices)
    int st_cr[4], st_q[4];
#pragma unroll
    for (int k = 0; k < 4; k++) {
        int e = k * 256 + tid;       // float4 index within an 8x512 slice
        st_cr[k] = e >> 7;
        st_q[k]  = (e & 127) * 4;
    }

    // --- stage student tile as duplicated f32x2 pairs ---
    {
        const float* sb = stu + (size_t)bv_i * C_DIM * HW_DIM + p_i;
#pragma unroll
        for (int k = 0; k < 4; k++) {
            int idx = k * 256 + tid;          // 0..1023
            int c = idx >> 4, r = idx & (RTILE - 1);
            float v = sb[c * HW_DIM + r];
            sf2_s[c][r] = pack2(v, v);
        }
    }
    if (tid < RTILE) lab_s[tid] = labels[i0 + tid];
    __syncthreads();
    if (tid < RTILE) {
        float ss = 0.f;
#pragma unroll
        for (int c = 0; c < C_DIM; c++) {
            float lo, hi;
            unpack2(sf2_s[c][tid], lo, hi);
            ss += lo * lo;
        }
        sinv_s[tid] = rsqrtf(fmaxf(ss, 1e-24f));
    }
    // visibility of sinv_s before epilogue: covered by in-loop syncthreads

    float Z[4], S[4], CT[4];
#pragma unroll
    for (int r = 0; r < 4; r++) { Z[r] = 0.f; S[r] = 0.f; CT[r] = 0.f; }

    for (int chunk = 0; chunk < NIMG / JCHUNK; chunk++) {
        int jchunk = jbase + chunk * JCHUNK;
        int bv_j = jchunk >> 10;
        int p_j  = jchunk & (HW_DIM - 1);
        const float* tbase = tea + (size_t)bv_j * C_DIM * HW_DIM + p_j;

        unsigned long long acc[4][4];   // acc[rr][cp]
#pragma unroll
        for (int rr = 0; rr < 4; rr++)
#pragma unroll
            for (int cp = 0; cp < 4; cp++) acc[rr][cp] = 0ull;

        // slice 0 -> buffer 0
        float4 pf[4];
#pragma unroll
        for (int k = 0; k < 4; k++)
            pf[k] = *(const float4*)(tbase + st_cr[k] * HW_DIM + st_q[k]);
#pragma unroll
        for (int k = 0; k < 4; k++)
            *(float4*)&ts_s[0][st_cr[k]][st_q[k]] = pf[k];
        __syncthreads();

#pragma unroll 2
        for (int cs = 0; cs < C_DIM / CSLICE; cs++) {
            // prefetch next slice while computing this one
            if (cs < C_DIM / CSLICE - 1) {
                const float* nbase = tbase + (cs + 1) * CSLICE * HW_DIM;
#pragma unroll
                for (int k = 0; k < 4; k++)
                    pf[k] = *(const float4*)(nbase + st_cr[k] * HW_DIM + st_q[k]);
            }

            const float(*buf)[JCHUNK] = ts_s[cs & 1];
#pragma unroll
            for (int cr = 0; cr < CSLICE; cr++) {
                int c = cs * CSLICE + cr;
                ulonglong2 tA = *(const ulonglong2*)&buf[cr][cg * 8];
                ulonglong2 tB = *(const ulonglong2*)&buf[cr][cg * 8 + 4];
#pragma unroll
                for (int rr = 0; rr < 4; rr++) {
                    unsigned long long sp = sf2_s[c][rg * 4 + rr];  // LDS.64 dup pair
                    acc[rr][0] = ffma2(sp, tA.x, acc[rr][0]);
                    acc[rr][1] = ffma2(sp, tA.y, acc[rr][1]);
                    acc[rr][2] = ffma2(sp, tB.x, acc[rr][2]);
                    acc[rr][3] = ffma2(sp, tB.y, acc[rr][3]);
                }
            }

            if (cs < C_DIM / CSLICE - 1) {
#pragma unroll
                for (int k = 0; k < 4; k++)
                    *(float4*)&ts_s[(cs + 1) & 1][st_cr[k]][st_q[k]] = pf[k];
                __syncthreads();   // one sync per slice
            }
        }

        // epilogue: 8 cols x 4 rows
        int j0 = jchunk + cg * 8;
#pragma unroll
        for (int cp = 0; cp < 4; cp++) {
#pragma unroll
            for (int half = 0; half < 2; half++) {
                int j = j0 + cp * 2 + half;
                float tinv10 = g_tinv10[j];
                int lj = labels[j];
#pragma unroll
                for (int rr = 0; rr < 4; rr++) {
                    float dlo, dhi;
                    unpack2(acc[rr][cp], dlo, dhi);
                    float d = half ? dhi : dlo;
                    int r = rg * 4 + rr;
                    float l = d * tinv10 * sinv_s[r];   // logit in [-10,10]
                    float e = __expf(l - 10.f);         // fixed shift M=10
                    if (j != i0 + r) {
                        Z[rr] += e;
                        if (lj == lab_s[r]) { S[rr] += l; CT[rr] += 1.f; }
                    }
                }
            }
        }
    }

    // deterministic reduction (all lanes of a warp share rg)
#pragma unroll
    for (int rr = 0; rr < 4; rr++) {
#pragma unroll
        for (int off = 16; off > 0; off >>= 1) {
            Z[rr]  += __shfl_down_sync(0xffffffffu, Z[rr],  off);
            S[rr]  += __shfl_down_sync(0xffffffffu, S[rr],  off);
            CT[rr] += __shfl_down_sync(0xffffffffu, CT[rr], off);
        }
    }
    int warp = tid >> 5, lane = tid & 31;
    if (lane == 0) {
#pragma unroll
        for (int rr = 0; rr < 4; rr++) {
            redZ[warp][rr] = Z[rr]; redS[warp][rr] = S[rr]; redC[warp][rr] = CT[rr];
        }
    }
    __syncthreads();
    if (tid < RTILE) {
        int r = tid, g = r >> 2, rr = r & 3;     // warps 2g, 2g+1 hold row r
        float z  = redZ[2 * g][rr] + redZ[2 * g + 1][rr];
        float s  = redS[2 * g][rr] + redS[2 * g + 1][rr];
        float ct = redC[2 * g][rr] + redC[2 * g + 1][rr];
        g_mlpp[i0 + r] = (s - ct * (10.f + logf(z))) / (ct + 1e-8f);
        g_cnt[i0 + r]  = ct;
    }

    // ---- fused finalize: last block reduces (deterministic fixed-order sum) ----
    __threadfence();
    __syncthreads();
    if (tid == 0)
        islast = (atomicAdd(&g_ticket, 1u) == (unsigned)(gridDim.x - 1));
    __syncthreads();
    if (islast) {
        __shared__ float rt[256], rv[256], rb[256];
        float t = 0.f, nv = 0.f, nbv = 0.f;
        for (int i = tid; i < N_TOT; i += 256) {
            float ct = __ldcg(&g_cnt[i]);
            if (ct > 0.5f) {             // valid: numerator_sums > eps
                t  += __ldcg(&g_mlpp[i]);
                nv += 1.f;
                if (labels[i] != 0) nbv += 1.f;
            }
        }
        rt[tid] = t; rv[tid] = nv; rb[tid] = nbv;
        __syncthreads();
        for (int s = 128; s > 0; s >>= 1) {
            if (tid < s) { rt[tid] += rt[tid + s]; rv[tid] += rv[tid + s]; rb[tid] += rb[tid + s]; }
            __syncthreads();
        }
        if (tid == 0) {
            float loss = -rt[0] / rv[0];
            out[0] = loss * rb[0] / (rb[0] + 1e-8f);   // bg_anchors=False rescale
            g_ticket = 0;                               // reset for next replay
        }
    }
}

extern "C" void kernel_launch(void* const* d_in, const int* in_sizes, int n_in,
                              void* d_out, int out_size) {
    const float* stu    = (const float*)d_in[0];
    const float* tea    = (const float*)d_in[1];
    const int*   labels = (const int*)d_in[2];
    float* out = (float*)d_out;

    scl_tnorms_kernel<<<N_TOT / 128, 128>>>(tea);
    scl_main_kernel<<<N_TOT / RTILE, 256>>>(stu, tea, labels, out);
}

// round 11
// speedup vs baseline: 2.0563x; 2.0563x over previous
#include <cuda_runtime.h>
#include <cstdint>

// Problem constants: student/teacher [B=2, V=2, C=64, HW=1024], labels [2,2,1024]
#define N_TOT  4096   // B*V*HW
#define C_DIM  64
#define HW_DIM 1024
#define NIMG   2048   // V*HW  (only same-image pairs contribute)
#define RTILE  32     // anchor rows per block
#define JCHUNK 512    // columns per chunk (within one view)
#define CSLICE 8      // c-rows staged per smem slice

// Scratch (device globals: no allocation allowed)
__device__ float g_tinv10[N_TOT];      // 10 / ||t_j||
__device__ float g_mlpp[N_TOT];
__device__ float g_cnt[N_TOT];
__device__ unsigned int g_ticket = 0;  // last-block ticket (self-resetting)

// ---------- packed f32x2 helpers (Blackwell FFMA2 via PTX) ----------
__device__ __forceinline__ unsigned long long pack2(float lo, float hi) {
    unsigned long long r;
    asm("mov.b64 %0, {%1, %2};" : "=l"(r) : "f"(lo), "f"(hi));
    return r;
}
__device__ __forceinline__ void unpack2(unsigned long long v, float& lo, float& hi) {
    asm("mov.b64 {%0, %1}, %2;" : "=f"(lo), "=f"(hi) : "l"(v));
}
__device__ __forceinline__ unsigned long long ffma2(unsigned long long a,
                                                    unsigned long long b,
                                                    unsigned long long c) {
    unsigned long long d;
    asm("fma.rn.f32x2 %0, %1, %2, %3;" : "=l"(d) : "l"(a), "l"(b), "l"(c));
    return d;
}

// ---------- kernel 1: teacher inverse norms (128 blocks, max MLP) ----------
__global__ __launch_bounds__(32) void scl_tnorms_kernel(const float* __restrict__ tea) {
    int n = blockIdx.x * 32 + threadIdx.x;
    const float* base = tea + (size_t)(n >> 10) * C_DIM * HW_DIM + (n & (HW_DIM - 1));
    float ss = 0.f;
#pragma unroll
    for (int c = 0; c < C_DIM; c++) {
        float v = base[c * HW_DIM];
        ss += v * v;
    }
    g_tinv10[n] = 10.f * rsqrtf(fmaxf(ss, 1e-24f));
}

// ---------- kernel 2: fused GEMM + masked log-softmax + final reduce ----------
// Block = 32 anchor rows x 2048 cols (4 chunks of 512). Thread tile 8x8.
// tid: cg = tid & 63 -> cols {cg*4..+3} and {256+cg*4..+3} (conflict-free LDS.128)
//      rg = tid >> 6 -> rows rg*8 .. rg*8+7
__global__ __launch_bounds__(256) void scl_main_kernel(
    const float* __restrict__ stu, const float* __restrict__ tea,
    const int* __restrict__ labels, float* __restrict__ out) {
    __shared__ __align__(16) float ts_s[2][CSLICE][JCHUNK];          // double buffer 32KB
    __shared__ __align__(16) unsigned long long sf2_s[C_DIM][RTILE]; // student dup-pairs 16KB
    __shared__ float sinv_s[RTILE];
    __shared__ int   lab_s[RTILE];
    __shared__ float redZ[8][8], redS[8][8], redC[8][8];
    __shared__ int islast;

    int tid = threadIdx.x;
    int cg  = tid & 63;
    int rg  = tid >> 6;
    int i0  = blockIdx.x * RTILE;
    int bv_i = i0 >> 10;
    int p_i  = i0 & (HW_DIM - 1);
    int jbase = i0 & ~(NIMG - 1);

    // staging address split (per-thread, reused for all slices)
    int st_cr[4], st_q[4];
#pragma unroll
    for (int k = 0; k < 4; k++) {
        int e = k * 256 + tid;       // float4 index within an 8x512 slice
        st_cr[k] = e >> 7;
        st_q[k]  = (e & 127) * 4;
    }

    // --- stage student tile as duplicated f32x2 pairs: sf2_s[c][r] = (s,s) ---
    {
        const float* sb = stu + (size_t)bv_i * C_DIM * HW_DIM + p_i;
#pragma unroll
        for (int k = 0; k < 8; k++) {
            int idx = k * 256 + tid;          // 0..2047
            int c = idx >> 5, r = idx & (RTILE - 1);
            float v = sb[c * HW_DIM + r];
            sf2_s[c][r] = pack2(v, v);
        }
    }
    if (tid < RTILE) lab_s[tid] = labels[i0 + tid];
    __syncthreads();
    if (tid < RTILE) {
        float ss = 0.f;
#pragma unroll
        for (int c = 0; c < C_DIM; c++) {
            float lo, hi;
            unpack2(sf2_s[c][tid], lo, hi);
            ss += lo * lo;
        }
        sinv_s[tid] = rsqrtf(fmaxf(ss, 1e-24f));
    }
    // sinv_s/lab_s visibility for epilogue: covered by in-loop __syncthreads

    float Z[8], S[8], CT[8];
#pragma unroll
    for (int r = 0; r < 8; r++) { Z[r] = 0.f; S[r] = 0.f; CT[r] = 0.f; }

    for (int chunk = 0; chunk < NIMG / JCHUNK; chunk++) {
        int jchunk = jbase + chunk * JCHUNK;
        int bv_j = jchunk >> 10;
        int p_j  = jchunk & (HW_DIM - 1);
        const float* tbase = tea + (size_t)bv_j * C_DIM * HW_DIM + p_j;

        // acc[rr][cp]: f32x2 over col pairs {A.x, A.y, B.x, B.y}
        unsigned long long acc[8][4];
#pragma unroll
        for (int rr = 0; rr < 8; rr++)
#pragma unroll
            for (int cp = 0; cp < 4; cp++) acc[rr][cp] = 0ull;

        // slice 0 -> buffer 0
        float4 pf[4];
#pragma unroll
        for (int k = 0; k < 4; k++)
            pf[k] = *(const float4*)(tbase + st_cr[k] * HW_DIM + st_q[k]);
#pragma unroll
        for (int k = 0; k < 4; k++)
            *(float4*)&ts_s[0][st_cr[k]][st_q[k]] = pf[k];
        __syncthreads();

        for (int cs = 0; cs < C_DIM / CSLICE; cs++) {
            // prefetch next slice while computing this one
            if (cs < C_DIM / CSLICE - 1) {
                const float* nbase = tbase + (cs + 1) * CSLICE * HW_DIM;
#pragma unroll
                for (int k = 0; k < 4; k++)
                    pf[k] = *(const float4*)(nbase + st_cr[k] * HW_DIM + st_q[k]);
            }

            const float(*buf)[JCHUNK] = ts_s[cs & 1];
#pragma unroll
            for (int cr = 0; cr < CSLICE; cr++) {
                int c = cs * CSLICE + cr;
                // conflict-free: lane addresses contiguous 16B chunks
                ulonglong2 tA = *(const ulonglong2*)&buf[cr][cg * 4];        // cols cg*4..+3
                ulonglong2 tB = *(const ulonglong2*)&buf[cr][256 + cg * 4];  // +256
#pragma unroll
                for (int rr = 0; rr < 8; rr += 2) {
                    // two student dup-pairs per LDS.128 broadcast
                    ulonglong2 sp2 = *(const ulonglong2*)&sf2_s[c][rg * 8 + rr];
                    acc[rr][0]     = ffma2(sp2.x, tA.x, acc[rr][0]);
                    acc[rr][1]     = ffma2(sp2.x, tA.y, acc[rr][1]);
                    acc[rr][2]     = ffma2(sp2.x, tB.x, acc[rr][2]);
                    acc[rr][3]     = ffma2(sp2.x, tB.y, acc[rr][3]);
                    acc[rr + 1][0] = ffma2(sp2.y, tA.x, acc[rr + 1][0]);
                    acc[rr + 1][1] = ffma2(sp2.y, tA.y, acc[rr + 1][1]);
                    acc[rr + 1][2] = ffma2(sp2.y, tB.x, acc[rr + 1][2]);
                    acc[rr + 1][3] = ffma2(sp2.y, tB.y, acc[rr + 1][3]);
                }
            }

            if (cs < C_DIM / CSLICE - 1) {
#pragma unroll
                for (int k = 0; k < 4; k++)
                    *(float4*)&ts_s[(cs + 1) & 1][st_cr[k]][st_q[k]] = pf[k];
                __syncthreads();   // one barrier per slice
            }
        }

        // epilogue: 8 cols x 8 rows
#pragma unroll
        for (int cp = 0; cp < 4; cp++) {
#pragma unroll
            for (int half = 0; half < 2; half++) {
                int j = jchunk + ((cp >> 1) ? 256 : 0) + cg * 4 + (cp & 1) * 2 + half;
                float tinv10 = g_tinv10[j];
                int lj = labels[j];
#pragma unroll
                for (int rr = 0; rr < 8; rr++) {
                    float dlo, dhi;
                    unpack2(acc[rr][cp], dlo, dhi);
                    float d = half ? dhi : dlo;
                    int r = rg * 8 + rr;
                    float l = d * tinv10 * sinv_s[r];   // logit in [-10,10]
                    float e = __expf(l - 10.f);         // fixed shift M=10
                    if (j != i0 + r) {
                        Z[rr] += e;
                        if (lj == lab_s[r]) { S[rr] += l; CT[rr] += 1.f; }
                    }
                }
            }
        }
    }

    // deterministic reduction (all lanes of a warp share rg)
#pragma unroll
    for (int rr = 0; rr < 8; rr++) {
#pragma unroll
        for (int off = 16; off > 0; off >>= 1) {
            Z[rr]  += __shfl_down_sync(0xffffffffu, Z[rr],  off);
            S[rr]  += __shfl_down_sync(0xffffffffu, S[rr],  off);
            CT[rr] += __shfl_down_sync(0xffffffffu, CT[rr], off);
        }
    }
    int warp = tid >> 5, lane = tid & 31;
    if (lane == 0) {
#pragma unroll
        for (int rr = 0; rr < 8; rr++) {
            redZ[warp][rr] = Z[rr]; redS[warp][rr] = S[rr]; redC[warp][rr] = CT[rr];
        }
    }
    __syncthreads();
    if (tid < RTILE) {
        int r = tid, g = r >> 3, rr = r & 7;     // warps 2g, 2g+1 hold row r
        float z  = redZ[2 * g][rr] + redZ[2 * g + 1][rr];
        float s  = redS[2 * g][rr] + redS[2 * g + 1][rr];
        float ct = redC[2 * g][rr] + redC[2 * g + 1][rr];
        g_mlpp[i0 + r] = (s - ct * (10.f + logf(z))) / (ct + 1e-8f);
        g_cnt[i0 + r]  = ct;
    }

    // ---- fused finalize: last block reduces (deterministic fixed-order sum) ----
    __threadfence();
    __syncthreads();
    if (tid == 0)
        islast = (atomicAdd(&g_ticket, 1u) == (unsigned)(gridDim.x - 1));
    __syncthreads();
    if (islast) {
        __shared__ float rt[256], rv[256], rb[256];
        float t = 0.f, nv = 0.f, nbv = 0.f;
        for (int i = tid; i < N_TOT; i += 256) {
            float ct = __ldcg(&g_cnt[i]);
            if (ct > 0.5f) {             // valid: numerator_sums > eps
                t  += __ldcg(&g_mlpp[i]);
                nv += 1.f;
                if (labels[i] != 0) nbv += 1.f;
            }
        }
        rt[tid] = t; rv[tid] = nv; rb[tid] = nbv;
        __syncthreads();
        for (int s = 128; s > 0; s >>= 1) {
            if (tid < s) { rt[tid] += rt[tid + s]; rv[tid] += rv[tid + s]; rb[tid] += rb[tid + s]; }
            __syncthreads();
        }
        if (tid == 0) {
            float loss = -rt[0] / rv[0];
            out[0] = loss * rb[0] / (rb[0] + 1e-8f);   // bg_anchors=False rescale
            g_ticket = 0;                               // reset for next replay
        }
    }
}

extern "C" void kernel_launch(void* const* d_in, const int* in_sizes, int n_in,
                              void* d_out, int out_size) {
    const float* stu    = (const float*)d_in[0];
    const float* tea    = (const float*)d_in[1];
    const int*   labels = (const int*)d_in[2];
    float* out = (float*)d_out;

    scl_tnorms_kernel<<<N_TOT / 32, 32>>>(tea);
    scl_main_kernel<<<N_TOT / RTILE, 256>>>(stu, tea, labels, out);
}

// round 13
// speedup vs baseline: 2.2856x; 1.1115x over previous
#include <cuda_runtime.h>
#include <cstdint>

// Problem constants: student/teacher [B=2, V=2, C=64, HW=1024], labels [2,2,1024]
#define N_TOT  4096   // B*V*HW
#define C_DIM  64
#define HW_DIM 1024
#define NIMG   2048   // V*HW  (only same-image pairs contribute)
#define RTILE  32     // anchor rows per block
#define JCHUNK 1024   // columns per chunk (= one view)
#define CSLICE 4      // c-rows staged per smem slice
#define NTHR   512

// Scratch (device globals: no allocation allowed)
__device__ float g_tinv10[N_TOT];      // 10 / ||t_j||
__device__ float g_mlpp[N_TOT];
__device__ float g_cnt[N_TOT];
__device__ unsigned int g_ticket = 0;  // last-block ticket (self-resetting)

// ---------- packed f32x2 helpers (Blackwell FFMA2 via PTX) ----------
__device__ __forceinline__ unsigned long long pack2(float lo, float hi) {
    unsigned long long r;
    asm("mov.b64 %0, {%1, %2};" : "=l"(r) : "f"(lo), "f"(hi));
    return r;
}
__device__ __forceinline__ void unpack2(unsigned long long v, float& lo, float& hi) {
    asm("mov.b64 {%0, %1}, %2;" : "=f"(lo), "=f"(hi) : "l"(v));
}
__device__ __forceinline__ unsigned long long ffma2(unsigned long long a,
                                                    unsigned long long b,
                                                    unsigned long long c) {
    unsigned long long d;
    asm("fma.rn.f32x2 %0, %1, %2, %3;" : "=l"(d) : "l"(a), "l"(b), "l"(c));
    return d;
}

// ---------- kernel 1: teacher inverse norms ----------
__global__ __launch_bounds__(32) void scl_tnorms_kernel(const float* __restrict__ tea) {
    int n = blockIdx.x * 32 + threadIdx.x;
    const float* base = tea + (size_t)(n >> 10) * C_DIM * HW_DIM + (n & (HW_DIM - 1));
    float ss = 0.f;
#pragma unroll
    for (int c = 0; c < C_DIM; c++) {
        float v = base[c * HW_DIM];
        ss += v * v;
    }
    g_tinv10[n] = 10.f * rsqrtf(fmaxf(ss, 1e-24f));
}

// ---------- kernel 2: fused GEMM + masked log-softmax + final reduce ----------
// 512 threads. Block = 32 rows x 2048 cols (2 chunks of 1024).
// Thread tile: 16 rows (f32x2 row-pairs) x 4 cols.
// cg = tid & 255 -> cols cg*4..+3 within chunk; rg = tid >> 8 -> rows rg*16..+15.
__global__ __launch_bounds__(NTHR) void scl_main_kernel(
    const float* __restrict__ stu, const float* __restrict__ tea,
    const int* __restrict__ labels, float* __restrict__ out) {
    __shared__ __align__(16) float ts_s[2][CSLICE][JCHUNK];   // 32 KB double buffer
    __shared__ __align__(16) float sf_s[C_DIM][RTILE];        // 8 KB student tile (raw)
    __shared__ float sinv_s[RTILE];
    __shared__ int   lab_s[RTILE];
    __shared__ float redZ[16][16], redS[16][16], redC[16][16];
    __shared__ int islast;

    int tid = threadIdx.x;
    int cg  = tid & 255;
    int rg  = tid >> 8;              // 0 or 1
    int i0  = blockIdx.x * RTILE;
    int bv_i = i0 >> 10;
    int p_i  = i0 & (HW_DIM - 1);
    int jbase = i0 & ~(NIMG - 1);

    // staging: slice = 4 c-rows x 1024 cols = 1024 float4; 2 per thread
    int st_cr[2], st_q[2];
#pragma unroll
    for (int k = 0; k < 2; k++) {
        int e = k * NTHR + tid;
        st_cr[k] = e >> 8;
        st_q[k]  = (e & 255) * 4;
    }

    // --- stage raw student tile sf_s[c][r] ---
    {
        const float* sb = stu + (size_t)bv_i * C_DIM * HW_DIM + p_i;
#pragma unroll
        for (int k = 0; k < 4; k++) {
            int idx = k * NTHR + tid;         // 0..2047
            int c = idx >> 5, r = idx & (RTILE - 1);
            sf_s[c][r] = sb[c * HW_DIM + r];
        }
    }
    if (tid < RTILE) lab_s[tid] = labels[i0 + tid];
    __syncthreads();
    if (tid < RTILE) {
        float ss = 0.f;
#pragma unroll
        for (int c = 0; c < C_DIM; c++) {
            float v = sf_s[c][tid];
            ss += v * v;
        }
        sinv_s[tid] = rsqrtf(fmaxf(ss, 1e-24f));
    }
    // sinv_s visibility before first epilogue: guarded by in-loop barriers

    for (int chunk = 0; chunk < NIMG / JCHUNK; chunk++) {
        int jchunk = jbase + chunk * JCHUNK;
        const float* tbase = tea + (size_t)(jchunk >> 10) * C_DIM * HW_DIM;

        // acc[rp][col]: f32x2 over row pair (2rp, 2rp+1)
        unsigned long long acc[8][4];
#pragma unroll
        for (int rp = 0; rp < 8; rp++)
#pragma unroll
            for (int col = 0; col < 4; col++) acc[rp][col] = 0ull;

        // slice 0 -> buffer 0
        float4 pf[2];
#pragma unroll
        for (int k = 0; k < 2; k++)
            pf[k] = *(const float4*)(tbase + st_cr[k] * HW_DIM + st_q[k]);
#pragma unroll
        for (int k = 0; k < 2; k++)
            *(float4*)&ts_s[0][st_cr[k]][st_q[k]] = pf[k];
        __syncthreads();

        const int NSLICE = C_DIM / CSLICE;   // 16
        for (int cs = 0; cs < NSLICE; cs++) {
            if (cs < NSLICE - 1) {
                const float* nbase = tbase + (cs + 1) * CSLICE * HW_DIM;
#pragma unroll
                for (int k = 0; k < 2; k++)
                    pf[k] = *(const float4*)(nbase + st_cr[k] * HW_DIM + st_q[k]);
            }

            const float(*buf)[JCHUNK] = ts_s[cs & 1];
#pragma unroll
            for (int cr = 0; cr < CSLICE; cr++) {
                int c = cs * CSLICE + cr;
                // teacher: 4 cols, one conflict-free LDS.128, dup-packed
                float4 tv = *(const float4*)&buf[cr][cg * 4];
                unsigned long long tp0 = pack2(tv.x, tv.x);
                unsigned long long tp1 = pack2(tv.y, tv.y);
                unsigned long long tp2 = pack2(tv.z, tv.z);
                unsigned long long tp3 = pack2(tv.w, tv.w);
#pragma unroll
                for (int rp = 0; rp < 8; rp += 2) {
                    // student: natural row pairs via LDS.128 broadcast (no MOVs)
                    ulonglong2 sp = *(const ulonglong2*)&sf_s[c][rg * 16 + rp * 2];
                    acc[rp][0]     = ffma2(sp.x, tp0, acc[rp][0]);
                    acc[rp][1]     = ffma2(sp.x, tp1, acc[rp][1]);
                    acc[rp][2]     = ffma2(sp.x, tp2, acc[rp][2]);
                    acc[rp][3]     = ffma2(sp.x, tp3, acc[rp][3]);
                    acc[rp + 1][0] = ffma2(sp.y, tp0, acc[rp + 1][0]);
                    acc[rp + 1][1] = ffma2(sp.y, tp1, acc[rp + 1][1]);
                    acc[rp + 1][2] = ffma2(sp.y, tp2, acc[rp + 1][2]);
                    acc[rp + 1][3] = ffma2(sp.y, tp3, acc[rp + 1][3]);
                }
            }

            if (cs < NSLICE - 1) {
#pragma unroll
                for (int k = 0; k < 2; k++)
                    *(float4*)&ts_s[(cs + 1) & 1][st_cr[k]][st_q[k]] = pf[k];
                __syncthreads();   // one barrier per slice
            }
        }

        // ---- per-chunk epilogue: 4 cols x 16 rows ----
        float Zc[16], Sc[16], Cc[16];
#pragma unroll
        for (int r = 0; r < 16; r++) { Zc[r] = 0.f; Sc[r] = 0.f; Cc[r] = 0.f; }

#pragma unroll
        for (int col = 0; col < 4; col++) {
            int j = jchunk + cg * 4 + col;
            float tinv10 = g_tinv10[j];
            int lj = labels[j];
#pragma unroll
            for (int rp = 0; rp < 8; rp++) {
                float dlo, dhi;
                unpack2(acc[rp][col], dlo, dhi);
#pragma unroll
                for (int half = 0; half < 2; half++) {
                    int rr = rp * 2 + half;
                    int r = rg * 16 + rr;
                    float d = half ? dhi : dlo;
                    float l = d * tinv10 * sinv_s[r];   // logit in [-10,10]
                    float e = __expf(l - 10.f);         // fixed shift M=10
                    if (j != i0 + r) {
                        Zc[rr] += e;
                        if (lj == lab_s[r]) { Sc[rr] += l; Cc[rr] += 1.f; }
                    }
                }
            }
        }

        // warp shuffle reduce (all lanes of a warp share rg), then smem accumulate
#pragma unroll
        for (int rr = 0; rr < 16; rr++) {
#pragma unroll
            for (int off = 16; off > 0; off >>= 1) {
                Zc[rr] += __shfl_down_sync(0xffffffffu, Zc[rr], off);
                Sc[rr] += __shfl_down_sync(0xffffffffu, Sc[rr], off);
                Cc[rr] += __shfl_down_sync(0xffffffffu, Cc[rr], off);
            }
        }
        int warp = tid >> 5, lane = tid & 31;
        if (lane == 0) {
            if (chunk == 0) {
#pragma unroll
                for (int rr = 0; rr < 16; rr++) {
                    redZ[warp][rr] = Zc[rr]; redS[warp][rr] = Sc[rr]; redC[warp][rr] = Cc[rr];
                }
            } else {
#pragma unroll
                for (int rr = 0; rr < 16; rr++) {
                    redZ[warp][rr] += Zc[rr]; redS[warp][rr] += Sc[rr]; redC[warp][rr] += Cc[rr];
                }
            }
        }
    }

    __syncthreads();
    if (tid < RTILE) {
        int r = tid, g = r >> 4, rr = r & 15;    // warps 8g..8g+7 hold row r
        float z = 0.f, s = 0.f, ct = 0.f;
#pragma unroll
        for (int w = 0; w < 8; w++) {
            z  += redZ[g * 8 + w][rr];
            s  += redS[g * 8 + w][rr];
            ct += redC[g * 8 + w][rr];
        }
        g_mlpp[i0 + r] = (s - ct * (10.f + logf(z))) / (ct + 1e-8f);
        g_cnt[i0 + r]  = ct;
    }

    // ---- fused finalize: last block reduces (deterministic fixed-order sum) ----
    __threadfence();
    __syncthreads();
    if (tid == 0)
        islast = (atomicAdd(&g_ticket, 1u) == (unsigned)(gridDim.x - 1));
    __syncthreads();
    if (islast) {
        __shared__ float rt[NTHR], rv[NTHR], rb[NTHR];
        float t = 0.f, nv = 0.f, nbv = 0.f;
        for (int i = tid; i < N_TOT; i += NTHR) {
            float ct = __ldcg(&g_cnt[i]);
            if (ct > 0.5f) {             // valid: numerator_sums > eps
                t  += __ldcg(&g_mlpp[i]);
                nv += 1.f;
                if (labels[i] != 0) nbv += 1.f;
            }
        }
        rt[tid] = t; rv[tid] = nv; rb[tid] = nbv;
        __syncthreads();
        for (int s = NTHR / 2; s > 0; s >>= 1) {
            if (tid < s) { rt[tid] += rt[tid + s]; rv[tid] += rv[tid + s]; rb[tid] += rb[tid + s]; }
            __syncthreads();
        }
        if (tid == 0) {
            float loss = -rt[0] / rv[0];
            out[0] = loss * rb[0] / (rb[0] + 1e-8f);   // bg_anchors=False rescale
            g_ticket = 0;                               // reset for next replay
        }
    }
}

extern "C" void kernel_launch(void* const* d_in, const int* in_sizes, int n_in,
                              void* d_out, int out_size) {
    const float* stu    = (const float*)d_in[0];
    const float* tea    = (const float*)d_in[1];
    const int*   labels = (const int*)d_in[2];
    float* out = (float*)d_out;

    scl_tnorms_kernel<<<N_TOT / 32, 32>>>(tea);
    scl_main_kernel<<<N_TOT / RTILE, NTHR>>>(stu, tea, labels, out);
}

// round 14
// speedup vs baseline: 2.3094x; 1.0104x over previous
#include <cuda_runtime.h>
#include <cstdint>

// Problem constants: student/teacher [B=2, V=2, C=64, HW=1024], labels [2,2,1024]
#define N_TOT  4096   // B*V*HW
#define C_DIM  64
#define HW_DIM 1024
#define NIMG   2048   // V*HW  (only same-image pairs contribute)
#define RTILE  32     // anchor rows per block
#define JCHUNK 1024   // columns per chunk (= one view)
#define CSLICE 8      // c-rows staged per smem slice
#define NTHR   512
#define DYN_SMEM (2 * CSLICE * JCHUNK * 4 + C_DIM * RTILE * 8)  // 64KB ts + 16KB sf2

// Scratch (device globals: no allocation allowed)
__device__ float g_tinv10[N_TOT];      // 10 / ||t_j||
__device__ float g_mlpp[N_TOT];
__device__ float g_cnt[N_TOT];
__device__ unsigned int g_ticket = 0;  // last-block ticket (self-resetting)

// ---------- packed f32x2 helpers (Blackwell FFMA2 via PTX) ----------
__device__ __forceinline__ unsigned long long pack2(float lo, float hi) {
    unsigned long long r;
    asm("mov.b64 %0, {%1, %2};" : "=l"(r) : "f"(lo), "f"(hi));
    return r;
}
__device__ __forceinline__ void unpack2(unsigned long long v, float& lo, float& hi) {
    asm("mov.b64 {%0, %1}, %2;" : "=f"(lo), "=f"(hi) : "l"(v));
}
__device__ __forceinline__ unsigned long long ffma2(unsigned long long a,
                                                    unsigned long long b,
                                                    unsigned long long c) {
    unsigned long long d;
    asm("fma.rn.f32x2 %0, %1, %2, %3;" : "=l"(d) : "l"(a), "l"(b), "l"(c));
    return d;
}

// ---------- kernel 1: teacher inverse norms ----------
__global__ __launch_bounds__(32) void scl_tnorms_kernel(const float* __restrict__ tea) {
    int n = blockIdx.x * 32 + threadIdx.x;
    const float* base = tea + (size_t)(n >> 10) * C_DIM * HW_DIM + (n & (HW_DIM - 1));
    float ss = 0.f;
#pragma unroll
    for (int c = 0; c < C_DIM; c++) {
        float v = base[c * HW_DIM];
        ss += v * v;
    }
    g_tinv10[n] = 10.f * rsqrtf(fmaxf(ss, 1e-24f));
}

// ---------- kernel 2: fused GEMM + masked log-softmax + final reduce ----------
// 512 threads, grid 128. Block = 32 rows x 2048 cols (2 chunks of 1024).
// Thread tile 8 rows x 8 cols. cg = tid & 127 -> cols {cg*4..+3} and {512+cg*4..+3}
// (16B lane stride: conflict-free LDS.128). rg = tid >> 7 -> rows rg*8..+7.
// Student staged as dup-pairs (s,s); teacher cols read as natural f32x2 pairs.
// Inner loop has ZERO pack MOVs.
__global__ __launch_bounds__(NTHR) void scl_main_kernel(
    const float* __restrict__ stu, const float* __restrict__ tea,
    const int* __restrict__ labels, float* __restrict__ out) {
    extern __shared__ __align__(16) char dynsmem[];
    float (*ts_s)[CSLICE][JCHUNK] = (float (*)[CSLICE][JCHUNK])dynsmem;          // 64 KB
    unsigned long long (*sf2_s)[RTILE] =
        (unsigned long long (*)[RTILE])(dynsmem + 2 * CSLICE * JCHUNK * 4);      // 16 KB

    __shared__ float sinv_s[RTILE];
    __shared__ int   lab_s[RTILE];
    __shared__ float redZ[16][8], redS[16][8], redC[16][8];
    __shared__ int islast;

    int tid = threadIdx.x;
    int cg  = tid & 127;
    int rg  = tid >> 7;              // 0..3
    int i0  = blockIdx.x * RTILE;
    int bv_i = i0 >> 10;
    int p_i  = i0 & (HW_DIM - 1);
    int jbase = i0 & ~(NIMG - 1);

    // staging: slice = 8 c-rows x 1024 cols = 2048 float4; 4 per thread
    int st_cr[4], st_q[4];
#pragma unroll
    for (int k = 0; k < 4; k++) {
        int e = k * NTHR + tid;
        st_cr[k] = e >> 8;
        st_q[k]  = (e & 255) * 4;
    }

    // --- stage student tile as dup-pairs sf2_s[c][r] = (s,s) ---
    {
        const float* sb = stu + (size_t)bv_i * C_DIM * HW_DIM + p_i;
#pragma unroll
        for (int k = 0; k < 4; k++) {
            int idx = k * NTHR + tid;         // 0..2047
            int c = idx >> 5, r = idx & (RTILE - 1);
            float v = sb[c * HW_DIM + r];
            sf2_s[c][r] = pack2(v, v);
        }
    }
    if (tid < RTILE) lab_s[tid] = labels[i0 + tid];
    __syncthreads();
    if (tid < RTILE) {
        float ss = 0.f;
#pragma unroll
        for (int c = 0; c < C_DIM; c++) {
            float lo, hi;
            unpack2(sf2_s[c][tid], lo, hi);
            ss += lo * lo;
        }
        sinv_s[tid] = rsqrtf(fmaxf(ss, 1e-24f));
    }
    // sinv_s/lab_s visibility before first epilogue: guarded by in-loop barriers

    for (int chunk = 0; chunk < NIMG / JCHUNK; chunk++) {
        int jchunk = jbase + chunk * JCHUNK;
        const float* tbase = tea + (size_t)(jchunk >> 10) * C_DIM * HW_DIM;

        // acc[rr][cp]: f32x2 over teacher col pair; rr = row within 8-row group
        unsigned long long acc[8][4];
#pragma unroll
        for (int rr = 0; rr < 8; rr++)
#pragma unroll
            for (int cp = 0; cp < 4; cp++) acc[rr][cp] = 0ull;

        // slice 0 -> buffer 0
        float4 pf[4];
#pragma unroll
        for (int k = 0; k < 4; k++)
            pf[k] = *(const float4*)(tbase + st_cr[k] * HW_DIM + st_q[k]);
#pragma unroll
        for (int k = 0; k < 4; k++)
            *(float4*)&ts_s[0][st_cr[k]][st_q[k]] = pf[k];
        __syncthreads();

        const int NSLICE = C_DIM / CSLICE;   // 8
        for (int cs = 0; cs < NSLICE; cs++) {
            if (cs < NSLICE - 1) {
                const float* nbase = tbase + (cs + 1) * CSLICE * HW_DIM;
#pragma unroll
                for (int k = 0; k < 4; k++)
                    pf[k] = *(const float4*)(nbase + st_cr[k] * HW_DIM + st_q[k]);
            }

            const float(*buf)[JCHUNK] = ts_s[cs & 1];
#pragma unroll
            for (int cr = 0; cr < CSLICE; cr++) {
                int c = cs * CSLICE + cr;
                // teacher: natural col-pairs via two conflict-free LDS.128
                ulonglong2 tA = *(const ulonglong2*)&buf[cr][cg * 4];         // cols cg*4..+3
                ulonglong2 tB = *(const ulonglong2*)&buf[cr][512 + cg * 4];   // +512
#pragma unroll
                for (int rr = 0; rr < 8; rr += 2) {
                    // student dup-pairs: one LDS.128 broadcast = rows rr, rr+1
                    ulonglong2 sp = *(const ulonglong2*)&sf2_s[c][rg * 8 + rr];
                    acc[rr][0]     = ffma2(sp.x, tA.x, acc[rr][0]);
                    acc[rr][1]     = ffma2(sp.x, tA.y, acc[rr][1]);
                    acc[rr][2]     = ffma2(sp.x, tB.x, acc[rr][2]);
                    acc[rr][3]     = ffma2(sp.x, tB.y, acc[rr][3]);
                    acc[rr + 1][0] = ffma2(sp.y, tA.x, acc[rr + 1][0]);
                    acc[rr + 1][1] = ffma2(sp.y, tA.y, acc[rr + 1][1]);
                    acc[rr + 1][2] = ffma2(sp.y, tB.x, acc[rr + 1][2]);
                    acc[rr + 1][3] = ffma2(sp.y, tB.y, acc[rr + 1][3]);
                }
            }

            if (cs < NSLICE - 1) {
#pragma unroll
                for (int k = 0; k < 4; k++)
                    *(float4*)&ts_s[(cs + 1) & 1][st_cr[k]][st_q[k]] = pf[k];
                __syncthreads();   // one barrier per slice (7 per chunk)
            }
        }

        // ---- per-chunk epilogue: 8 cols x 8 rows ----
        float Zc[8], Sc[8], Cc[8];
#pragma unroll
        for (int r = 0; r < 8; r++) { Zc[r] = 0.f; Sc[r] = 0.f; Cc[r] = 0.f; }

#pragma unroll
        for (int cp = 0; cp < 4; cp++) {
#pragma unroll
            for (int half = 0; half < 2; half++) {
                int j = jchunk + ((cp >> 1) ? 512 : 0) + cg * 4 + (cp & 1) * 2 + half;
                float tinv10 = g_tinv10[j];
                int lj = labels[j];
#pragma unroll
                for (int rr = 0; rr < 8; rr++) {
                    float dlo, dhi;
                    unpack2(acc[rr][cp], dlo, dhi);
                    float d = half ? dhi : dlo;
                    int r = rg * 8 + rr;
                    float l = d * tinv10 * sinv_s[r];   // logit in [-10,10]
                    float e = __expf(l - 10.f);         // fixed shift M=10
                    if (j != i0 + r) {
                        Zc[rr] += e;
                        if (lj == lab_s[r]) { Sc[rr] += l; Cc[rr] += 1.f; }
                    }
                }
            }
        }

        // warp shuffle reduce (all lanes of a warp share rg), accumulate in smem
#pragma unroll
        for (int rr = 0; rr < 8; rr++) {
#pragma unroll
            for (int off = 16; off > 0; off >>= 1) {
                Zc[rr] += __shfl_down_sync(0xffffffffu, Zc[rr], off);
                Sc[rr] += __shfl_down_sync(0xffffffffu, Sc[rr], off);
                Cc[rr] += __shfl_down_sync(0xffffffffu, Cc[rr], off);
            }
        }
        int warp = tid >> 5, lane = tid & 31;
        if (lane == 0) {
            if (chunk == 0) {
#pragma unroll
                for (int rr = 0; rr < 8; rr++) {
                    redZ[warp][rr] = Zc[rr]; redS[warp][rr] = Sc[rr]; redC[warp][rr] = Cc[rr];
                }
            } else {
#pragma unroll
                for (int rr = 0; rr < 8; rr++) {
                    redZ[warp][rr] += Zc[rr]; redS[warp][rr] += Sc[rr]; redC[warp][rr] += Cc[rr];
                }
            }
        }
    }

    __syncthreads();
    if (tid < RTILE) {
        int r = tid, g = r >> 3, rr = r & 7;     // warps 4g..4g+3 hold row r
        float z = 0.f, s = 0.f, ct = 0.f;
#pragma unroll
        for (int w = 0; w < 4; w++) {
            z  += redZ[g * 4 + w][rr];
            s  += redS[g * 4 + w][rr];
            ct += redC[g * 4 + w][rr];
        }
        g_mlpp[i0 + r] = (s - ct * (10.f + logf(z))) / (ct + 1e-8f);
        g_cnt[i0 + r]  = ct;
    }

    // ---- fused finalize: last block reduces (deterministic fixed-order sum) ----
    __threadfence();
    __syncthreads();
    if (tid == 0)
        islast = (atomicAdd(&g_ticket, 1u) == (unsigned)(gridDim.x - 1));
    __syncthreads();
    if (islast) {
        __shared__ float rt[NTHR], rv[NTHR], rb[NTHR];
        float t = 0.f, nv = 0.f, nbv = 0.f;
        for (int i = tid; i < N_TOT; i += NTHR) {
            float ct = __ldcg(&g_cnt[i]);
            if (ct > 0.5f) {             // valid: numerator_sums > eps
                t  += __ldcg(&g_mlpp[i]);
                nv += 1.f;
                if (labels[i] != 0) nbv += 1.f;
            }
        }
        rt[tid] = t; rv[tid] = nv; rb[tid] = nbv;
        __syncthreads();
        for (int s = NTHR / 2; s > 0; s >>= 1) {
            if (tid < s) { rt[tid] += rt[tid + s]; rv[tid] += rv[tid + s]; rb[tid] += rb[tid + s]; }
            __syncthreads();
        }
        if (tid == 0) {
            float loss = -rt[0] / rv[0];
            out[0] = loss * rb[0] / (rb[0] + 1e-8f);   // bg_anchors=False rescale
            g_ticket = 0;                               // reset for next replay
        }
    }
}

extern "C" void kernel_launch(void* const* d_in, const int* in_sizes, int n_in,
                              void* d_out, int out_size) {
    const float* stu    = (const float*)d_in[0];
    const float* tea    = (const float*)d_in[1];
    const int*   labels = (const int*)d_in[2];
    float* out = (float*)d_out;

    cudaFuncSetAttribute(scl_main_kernel,
                         cudaFuncAttributeMaxDynamicSharedMemorySize, DYN_SMEM);

    scl_tnorms_kernel<<<N_TOT / 32, 32>>>(tea);
    scl_main_kernel<<<N_TOT / RTILE, NTHR, DYN_SMEM>>>(stu, tea, labels, out);
}